// round 14
// baseline (speedup 1.0000x reference)
#include <cuda_runtime.h>
#include <cuda_fp16.h>
#include <cstdint>

#define NUM_NEURONS 8192
#define INPUT_SIZE  8192
#define BATCH       2048

#define THREADS 1024
#define GRIDB   128                // blocks; each owns exactly 4 groups
#define GPB     4                  // groups (of 4 rows) per block
#define F4ROW   (INPUT_SIZE / 4)   // 2048 float4 per row

// Per-neuron collapsed coefficients packed half2: {A,B},{C,D}
__device__ uint2 g_cffh[NUM_NEURONS];

__constant__ float4 c_op[16] = {
    {0.f,  0.f,  0.f,  0.f}, {0.f,  0.f,  0.f,  1.f},
    {0.f,  1.f,  0.f, -1.f}, {0.f,  1.f,  0.f,  0.f},
    {0.f,  0.f,  1.f, -1.f}, {0.f,  0.f,  1.f,  0.f},
    {0.f,  1.f,  1.f, -2.f}, {0.f,  1.f,  1.f, -1.f},
    {1.f, -1.f, -1.f,  1.f}, {1.f, -1.f, -1.f,  2.f},
    {1.f,  0.f, -1.f,  0.f}, {1.f,  0.f, -1.f,  1.f},
    {1.f, -1.f,  0.f,  0.f}, {1.f, -1.f,  0.f,  1.f},
    {1.f,  0.f,  0.f, -1.f}, {1.f,  0.f,  0.f,  0.f},
};

__device__ __forceinline__ unsigned h2u(__half2 h) {
    return *reinterpret_cast<unsigned*>(&h);
}
__device__ __forceinline__ __half2 u2h(unsigned u) {
    return *reinterpret_cast<__half2*>(&u);
}

// ---------------------------------------------------------------------------
// Warp-parallel coefficient precompute: 16 lanes per neuron (one per op).
// ---------------------------------------------------------------------------
__global__ void coeff_kernel(const float* __restrict__ w) {
    const int gt = blockIdx.x * blockDim.x + threadIdx.x;
    const int n = gt >> 4;
    const int j = gt & 15;
    if (n >= NUM_NEURONS) return;

    const float wv = __ldg(&w[(n << 4) + j]);
    float m = wv;
#pragma unroll
    for (int o = 8; o; o >>= 1) m = fmaxf(m, __shfl_xor_sync(0xFFFFFFFFu, m, o, 16));
    const float e = __expf(wv - m);
    float s = e;
#pragma unroll
    for (int o = 8; o; o >>= 1) s += __shfl_xor_sync(0xFFFFFFFFu, s, o, 16);
    const float p = e / s;

    const float4 c = c_op[j];
    float A = p * c.x, B = p * c.y, C = p * c.z, D = p * c.w;
#pragma unroll
    for (int o = 8; o; o >>= 1) {
        A += __shfl_xor_sync(0xFFFFFFFFu, A, o, 16);
        B += __shfl_xor_sync(0xFFFFFFFFu, B, o, 16);
        C += __shfl_xor_sync(0xFFFFFFFFu, C, o, 16);
        D += __shfl_xor_sync(0xFFFFFFFFu, D, o, 16);
    }
    if (j == 0)
        g_cffh[n] = make_uint2(h2u(__floats2half2_rn(A, B)),
                               h2u(__floats2half2_rn(C, D)));
}

// Pack two fp32 row-chunks (rows ra, rb; 4 columns each) into half2 and store
// at float4-column `col` of table `dst`. Conflict-free STS.128.
__device__ __forceinline__ void sts_pack(__half2* dst, int col, float4 ra, float4 rb) {
    reinterpret_cast<uint4*>(dst)[col] =
        make_uint4(h2u(__floats2half2_rn(ra.x, rb.x)),
                   h2u(__floats2half2_rn(ra.y, rb.y)),
                   h2u(__floats2half2_rn(ra.z, rb.z)),
                   h2u(__floats2half2_rn(ra.w, rb.w)));
}

// ---------------------------------------------------------------------------
// Persistent main kernel. 128 blocks x 1024 threads; each block owns exactly
// 4 groups of 4 batch rows. SMEM: 2 double-buffered half2 table sets,
// tabA = {r0,r1}, tabB = {r2,r3}: ONE LDS.32 gathers one index for TWO rows,
// i.e. 1 LDS per row per neuron (half of the fp32 scheme). Staging for group
// k+1 (LDG.128 -> half2 pack -> STS.128; no TMA, no smem re-read) is software
// pipelined into group k's gather slots in 8-register chunks. ONE
// __syncthreads per 4 rows. Coefficients are half2-packed, reloaded per
// group from L2 to keep regs <= 64 at 1024 threads.
// ---------------------------------------------------------------------------
__global__ __launch_bounds__(THREADS, 1) void logic_kernel(
    const float* __restrict__ x,
    const int*   __restrict__ idx,
    float* __restrict__ out)
{
    extern __shared__ __align__(16) __half2 tabs[];   // [2 bufs][2 tables][8192]

    const int tid = threadIdx.x;
    const int bid = blockIdx.x;
    const float4* x4  = reinterpret_cast<const float4*>(x);
    const uint4*  cf4 = reinterpret_cast<const uint4*>(g_cffh);  // 2 neurons/uint4

    // --- Preload packed gather indices (16-bit pairs) for this thread's 8 neurons ---
    uint32_t pidx[8];
    {
        const int4* idx4 = reinterpret_cast<const int4*>(idx);
#pragma unroll
        for (int g = 0; g < 2; g++) {
            const int nbase = g * 4096 + tid * 4;
            int4 ia = __ldg(&idx4[nbase / 2]);
            int4 ib = __ldg(&idx4[nbase / 2 + 1]);
            pidx[g * 4 + 0] = (uint32_t)ia.x | ((uint32_t)ia.y << 16);
            pidx[g * 4 + 1] = (uint32_t)ia.z | ((uint32_t)ia.w << 16);
            pidx[g * 4 + 2] = (uint32_t)ib.x | ((uint32_t)ib.y << 16);
            pidx[g * 4 + 3] = (uint32_t)ib.z | ((uint32_t)ib.w << 16);
        }
    }

    // --- Prologue: stage group bid*4 into buffer 0 ---
    {
        __half2* A0 = tabs;
        __half2* B0 = tabs + INPUT_SIZE;
        const size_t rb = (size_t)(bid * GPB) * 4 * F4ROW;
        float4 r0 = __ldg(x4 + rb + tid);
        float4 r1 = __ldg(x4 + rb + F4ROW + tid);
        float4 r2 = __ldg(x4 + rb + 2 * F4ROW + tid);
        float4 r3 = __ldg(x4 + rb + 3 * F4ROW + tid);
        sts_pack(A0, tid, r0, r1);
        sts_pack(B0, tid, r2, r3);
        r0 = __ldg(x4 + rb + 1024 + tid);
        r1 = __ldg(x4 + rb + F4ROW + 1024 + tid);
        r2 = __ldg(x4 + rb + 2 * F4ROW + 1024 + tid);
        r3 = __ldg(x4 + rb + 3 * F4ROW + 1024 + tid);
        sts_pack(A0, 1024 + tid, r0, r1);
        sts_pack(B0, 1024 + tid, r2, r3);
    }
    __syncthreads();

#pragma unroll
    for (int it = 0; it < GPB; it++) {
        const __half2* curA = tabs + (it & 1) * (2 * INPUT_SIZE);
        const __half2* curB = curA + INPUT_SIZE;
        __half2* nxtA = tabs + ((it + 1) & 1) * (2 * INPUT_SIZE);
        __half2* nxtB = nxtA + INPUT_SIZE;

        const int  gid = bid * GPB + it;
        const bool hv  = (it < GPB - 1);
        const size_t nrb = (size_t)(gid + 1) * 4 * F4ROW;   // next group rows
        float* obase = out + (size_t)(gid * 4) * NUM_NEURONS;

        float4 s0, s1;   // held staging chunk (8 regs)
        if (hv) { s0 = __ldg(x4 + nrb + tid); s1 = __ldg(x4 + nrb + F4ROW + tid); }

#pragma unroll
        for (int g = 0; g < 2; g++) {
            // coefficients for this group's 4 neurons (2 x uint4, L2-resident)
            const int nbase = g * 4096 + tid * 4;
            uint4 ca = __ldg(&cf4[nbase / 2]);
            uint4 cb = __ldg(&cf4[nbase / 2 + 1]);

            float4 q0, q1, q2, q3;             // rows 0..3, neurons nbase..+3
            float* p0 = reinterpret_cast<float*>(&q0);
            float* p1 = reinterpret_cast<float*>(&q1);
            float* p2 = reinterpret_cast<float*>(&q2);
            float* p3 = reinterpret_cast<float*>(&q3);

#pragma unroll
            for (int u = 0; u < 4; u++) {
                const uint32_t pk = pidx[g * 4 + u];
                const int i1 = pk & 0xFFFFu;
                const int i2 = pk >> 16;
                const float2 a01 = __half22float2(curA[i1]);   // {r0,r1} @ i1
                const float2 b01 = __half22float2(curA[i2]);   // {r0,r1} @ i2
                const float2 a23 = __half22float2(curB[i1]);   // {r2,r3} @ i1
                const float2 b23 = __half22float2(curB[i2]);
                const uint32_t cAB = (u < 2) ? ((u == 0) ? ca.x : ca.z)
                                             : ((u == 2) ? cb.x : cb.z);
                const uint32_t cCD = (u < 2) ? ((u == 0) ? ca.y : ca.w)
                                             : ((u == 2) ? cb.y : cb.w);
                const float2 AB = __half22float2(u2h(cAB));
                const float2 CD = __half22float2(u2h(cCD));
                p0[u] = fmaf(a01.x, fmaf(b01.x, CD.y, AB.y), fmaf(b01.x, CD.x, AB.x));
                p1[u] = fmaf(a01.y, fmaf(b01.y, CD.y, AB.y), fmaf(b01.y, CD.x, AB.x));
                p2[u] = fmaf(a23.x, fmaf(b23.x, CD.y, AB.y), fmaf(b23.x, CD.x, AB.x));
                p3[u] = fmaf(a23.y, fmaf(b23.y, CD.y, AB.y), fmaf(b23.y, CD.x, AB.x));

                // Software-pipelined staging: after half of each gather group,
                // commit the arrived chunk and issue the next one.
                if (u == 1 && hv) {
                    if (g == 0) {
                        sts_pack(nxtA, tid, s0, s1);                   // r0,r1 colA
                        s0 = __ldg(x4 + nrb + 2 * F4ROW + tid);        // r2,r3 colA
                        s1 = __ldg(x4 + nrb + 3 * F4ROW + tid);
                    } else {
                        sts_pack(nxtA, 1024 + tid, s0, s1);            // r0,r1 colB
                        s0 = __ldg(x4 + nrb + 2 * F4ROW + 1024 + tid); // r2,r3 colB
                        s1 = __ldg(x4 + nrb + 3 * F4ROW + 1024 + tid);
                    }
                }
            }

            const int o = g * 1024 + tid;      // coalesced float4 stores
            reinterpret_cast<float4*>(obase)[o]                   = q0;
            reinterpret_cast<float4*>(obase +     NUM_NEURONS)[o] = q1;
            reinterpret_cast<float4*>(obase + 2 * NUM_NEURONS)[o] = q2;
            reinterpret_cast<float4*>(obase + 3 * NUM_NEURONS)[o] = q3;

            if (hv) {
                if (g == 0) {
                    sts_pack(nxtB, tid, s0, s1);                       // r2,r3 colA
                    s0 = __ldg(x4 + nrb + 1024 + tid);                 // r0,r1 colB
                    s1 = __ldg(x4 + nrb + F4ROW + 1024 + tid);
                } else {
                    sts_pack(nxtB, 1024 + tid, s0, s1);                // r2,r3 colB
                }
            }
        }

        __syncthreads();   // gathers of it done; staging of it+1 visible
    }
}

extern "C" void kernel_launch(void* const* d_in, const int* in_sizes, int n_in,
                              void* d_out, int out_size) {
    const float* x    = (const float*)d_in[0];   // [2048, 8192] f32
    const float* w    = (const float*)d_in[1];   // [8192, 16]   f32
    const int*   conn = (const int*)d_in[2];     // [8192, 2]    i32
    float* out = (float*)d_out;                  // [2048, 8192] f32

    const int smem = 4 * INPUT_SIZE * sizeof(__half2);   // 128 KB
    cudaFuncSetAttribute(logic_kernel,
                         cudaFuncAttributeMaxDynamicSharedMemorySize, smem);

    coeff_kernel<<<(NUM_NEURONS * 16) / 256, 256>>>(w);
    logic_kernel<<<GRIDB, THREADS, smem>>>(x, conn, out);
}

// round 15
// speedup vs baseline: 1.2626x; 1.2626x over previous
#include <cuda_runtime.h>
#include <cuda_fp16.h>
#include <cstdint>

#define NUM_NEURONS 8192
#define INPUT_SIZE  8192
#define BATCH       2048

#define THREADS 512
#define NPT     16                 // neurons per thread (4 groups of 4)
#define GRIDB   296                // 2 blocks per SM
#define PAIRS   (BATCH / 2)        // 1024 row-pairs
#define PAIR_BYTES (2 * INPUT_SIZE * 4)   // 64 KB

// Per-neuron collapsed coefficients packed half2: {A,B},{C,D}
__device__ uint2 g_cffh[NUM_NEURONS];

__constant__ float4 c_op[16] = {
    {0.f,  0.f,  0.f,  0.f}, {0.f,  0.f,  0.f,  1.f},
    {0.f,  1.f,  0.f, -1.f}, {0.f,  1.f,  0.f,  0.f},
    {0.f,  0.f,  1.f, -1.f}, {0.f,  0.f,  1.f,  0.f},
    {0.f,  1.f,  1.f, -2.f}, {0.f,  1.f,  1.f, -1.f},
    {1.f, -1.f, -1.f,  1.f}, {1.f, -1.f, -1.f,  2.f},
    {1.f,  0.f, -1.f,  0.f}, {1.f,  0.f, -1.f,  1.f},
    {1.f, -1.f,  0.f,  0.f}, {1.f, -1.f,  0.f,  1.f},
    {1.f,  0.f,  0.f, -1.f}, {1.f,  0.f,  0.f,  0.f},
};

__device__ __forceinline__ unsigned h2u(__half2 h) {
    return *reinterpret_cast<unsigned*>(&h);
}
__device__ __forceinline__ __half2 u2h(unsigned u) {
    return *reinterpret_cast<__half2*>(&u);
}

// ---------------------------------------------------------------------------
// Warp-parallel coefficient precompute: 16 lanes per neuron (one per op).
// ---------------------------------------------------------------------------
__global__ void coeff_kernel(const float* __restrict__ w) {
    const int gt = blockIdx.x * blockDim.x + threadIdx.x;
    const int n = gt >> 4;
    const int j = gt & 15;
    if (n >= NUM_NEURONS) return;

    const float wv = __ldg(&w[(n << 4) + j]);
    float m = wv;
#pragma unroll
    for (int o = 8; o; o >>= 1) m = fmaxf(m, __shfl_xor_sync(0xFFFFFFFFu, m, o, 16));
    const float e = __expf(wv - m);
    float s = e;
#pragma unroll
    for (int o = 8; o; o >>= 1) s += __shfl_xor_sync(0xFFFFFFFFu, s, o, 16);
    const float p = e / s;

    const float4 c = c_op[j];
    float A = p * c.x, B = p * c.y, C = p * c.z, D = p * c.w;
#pragma unroll
    for (int o = 8; o; o >>= 1) {
        A += __shfl_xor_sync(0xFFFFFFFFu, A, o, 16);
        B += __shfl_xor_sync(0xFFFFFFFFu, B, o, 16);
        C += __shfl_xor_sync(0xFFFFFFFFu, C, o, 16);
        D += __shfl_xor_sync(0xFFFFFFFFu, D, o, 16);
    }
    if (j == 0)
        g_cffh[n] = make_uint2(h2u(__floats2half2_rn(A, B)),
                               h2u(__floats2half2_rn(C, D)));
}

// ---------------------------------------------------------------------------
// PTX helpers
// ---------------------------------------------------------------------------
__device__ __forceinline__ uint32_t smem_u32(const void* p) {
    uint32_t a;
    asm("{ .reg .u64 t; cvta.to.shared.u64 t, %1; cvt.u32.u64 %0, t; }"
        : "=r"(a) : "l"(p));
    return a;
}
__device__ __forceinline__ void mbar_init(uint32_t m, uint32_t cnt) {
    asm volatile("mbarrier.init.shared.b64 [%0], %1;" :: "r"(m), "r"(cnt) : "memory");
}
__device__ __forceinline__ void mbar_expect_tx(uint32_t m, uint32_t bytes) {
    asm volatile("mbarrier.arrive.expect_tx.shared.b64 _, [%0], %1;"
                 :: "r"(m), "r"(bytes) : "memory");
}
__device__ __forceinline__ void mbar_wait(uint32_t m, uint32_t phase) {
    asm volatile(
        "{\n\t.reg .pred P;\n\t"
        "WL_%=:\n\t"
        "mbarrier.try_wait.parity.acquire.cta.shared::cta.b64 P, [%0], %1, 0x989680;\n\t"
        "@P bra WD_%=;\n\t"
        "bra WL_%=;\n\t"
        "WD_%=:\n\t}"
        :: "r"(m), "r"(phase) : "memory");
}
__device__ __forceinline__ void tma_bulk_g2s(uint32_t dst_smem, const void* src,
                                             uint32_t bytes, uint32_t mbar) {
    asm volatile(
        "cp.async.bulk.shared::cluster.global.mbarrier::complete_tx::bytes "
        "[%0], [%1], %2, [%3];"
        :: "r"(dst_smem), "l"(src), "r"(bytes), "r"(mbar) : "memory");
}

// ---------------------------------------------------------------------------
// Main kernel: 296 blocks = 2 per SM, 512 threads each. Per block: 64 KB fp32
// TMA landing buffer + 32 KB half2 gather table (96 KB; 2 blocks fit in
// 228 KB). One LDS.32 gathers one index for BOTH rows of the pair. While one
// block stalls at its barriers / TMA wait, the co-resident block's warps keep
// the L1 crossbar busy — cross-block phase overlap, which single-block
// variants could never achieve (L1 util capped at ~60-68%).
// Per-block schedule: wait TMA(k) -> convert fbuf->xh -> barrier ->
// issue TMA(k+1) (fbuf free) -> gather/compute k -> barrier.
// Coefficients are half2-packed, loaded per group from L2 to keep regs<=64.
// ---------------------------------------------------------------------------
__global__ __launch_bounds__(THREADS, 2) void logic_kernel(
    const float* __restrict__ x,
    const int*   __restrict__ idx,
    float* __restrict__ out)
{
    extern __shared__ __align__(128) char smem[];
    float*   fbuf = reinterpret_cast<float*>(smem);                   // 64 KB
    __half2* xh   = reinterpret_cast<__half2*>(smem + PAIR_BYTES);    // 32 KB
    const uint32_t mbar = smem_u32(smem + PAIR_BYTES + INPUT_SIZE * 4);

    const int tid = threadIdx.x;
    const int bid = blockIdx.x;
    const uint4* cf4 = reinterpret_cast<const uint4*>(g_cffh);  // 2 neurons/uint4

    // --- Preload packed gather indices (u16 pairs) for 16 neurons ---
    uint32_t pidx[NPT];
    {
        const int4* idx4 = reinterpret_cast<const int4*>(idx);
#pragma unroll
        for (int g = 0; g < 4; g++) {
            const int nbase = g * 2048 + tid * 4;
            int4 ia = __ldg(&idx4[nbase / 2]);
            int4 ib = __ldg(&idx4[nbase / 2 + 1]);
            pidx[g * 4 + 0] = (uint32_t)ia.x | ((uint32_t)ia.y << 16);
            pidx[g * 4 + 1] = (uint32_t)ia.z | ((uint32_t)ia.w << 16);
            pidx[g * 4 + 2] = (uint32_t)ib.x | ((uint32_t)ib.y << 16);
            pidx[g * 4 + 3] = (uint32_t)ib.z | ((uint32_t)ib.w << 16);
        }
    }

    if (tid == 0) mbar_init(mbar, 1);
    __syncthreads();

    const int npairs = (PAIRS - bid + GRIDB - 1) / GRIDB;   // 3 or 4

    if (tid == 0) {
        mbar_expect_tx(mbar, PAIR_BYTES);
        tma_bulk_g2s(smem_u32(fbuf), x + (size_t)bid * 2 * INPUT_SIZE,
                     PAIR_BYTES, mbar);
    }

    for (int k = 0; k < npairs; k++) {
        mbar_wait(mbar, k & 1);

        // --- Convert: fp32 pair -> half2 {row0,row1}. Conflict-free vec. ---
        {
            const float4* fb4 = reinterpret_cast<const float4*>(fbuf);
            uint4* x4 = reinterpret_cast<uint4*>(xh);
#pragma unroll
            for (int i = 0; i < 4; i++) {
                const int c = i * THREADS + tid;
                float4 r0 = fb4[c];
                float4 r1 = fb4[c + 2048];
                x4[c] = make_uint4(h2u(__floats2half2_rn(r0.x, r1.x)),
                                   h2u(__floats2half2_rn(r0.y, r1.y)),
                                   h2u(__floats2half2_rn(r0.z, r1.z)),
                                   h2u(__floats2half2_rn(r0.w, r1.w)));
            }
        }
        __syncthreads();   // xh ready; fbuf dead

        if (tid == 0 && k + 1 < npairs) {
            mbar_expect_tx(mbar, PAIR_BYTES);
            tma_bulk_g2s(smem_u32(fbuf),
                         x + (size_t)(bid + (k + 1) * GRIDB) * 2 * INPUT_SIZE,
                         PAIR_BYTES, mbar);
        }

        // --- Gather + compute pair k ---
        const int p = bid + k * GRIDB;
        float4* o0 = reinterpret_cast<float4*>(out + (size_t)(2 * p)     * NUM_NEURONS);
        float4* o1 = reinterpret_cast<float4*>(out + (size_t)(2 * p + 1) * NUM_NEURONS);

#pragma unroll
        for (int g = 0; g < 4; g++) {
            const int nbase = g * 2048 + tid * 4;
            const uint4 ca = __ldg(&cf4[nbase / 2]);       // neurons nbase,+1
            const uint4 cb = __ldg(&cf4[nbase / 2 + 1]);   // neurons +2,+3

            float4 r0, r1;
            float* q0 = reinterpret_cast<float*>(&r0);
            float* q1 = reinterpret_cast<float*>(&r1);
#pragma unroll
            for (int u = 0; u < 4; u++) {
                const uint32_t pk = pidx[g * 4 + u];
                const float2 a1 = __half22float2(xh[pk & 0xFFFFu]);  // {r0,r1}@i1
                const float2 a2 = __half22float2(xh[pk >> 16]);     // {r0,r1}@i2
                const uint32_t cAB = (u == 0) ? ca.x : (u == 1) ? ca.z
                                   : (u == 2) ? cb.x : cb.z;
                const uint32_t cCD = (u == 0) ? ca.y : (u == 1) ? ca.w
                                   : (u == 2) ? cb.y : cb.w;
                const float2 AB = __half22float2(u2h(cAB));
                const float2 CD = __half22float2(u2h(cCD));
                q0[u] = fmaf(a1.x, fmaf(a2.x, CD.y, AB.y), fmaf(a2.x, CD.x, AB.x));
                q1[u] = fmaf(a1.y, fmaf(a2.y, CD.y, AB.y), fmaf(a2.y, CD.x, AB.x));
            }
            const int o = g * THREADS + tid;   // coalesced float4 stores
            o0[o] = r0;
            o1[o] = r1;
        }

        __syncthreads();   // gathers done before next convert overwrites xh
    }
}

extern "C" void kernel_launch(void* const* d_in, const int* in_sizes, int n_in,
                              void* d_out, int out_size) {
    const float* x    = (const float*)d_in[0];   // [2048, 8192] f32
    const float* w    = (const float*)d_in[1];   // [8192, 16]   f32
    const int*   conn = (const int*)d_in[2];     // [8192, 2]    i32
    float* out = (float*)d_out;                  // [2048, 8192] f32

    const int smem = PAIR_BYTES + INPUT_SIZE * 4 + 16;   // 96 KB + mbar
    cudaFuncSetAttribute(logic_kernel,
                         cudaFuncAttributeMaxDynamicSharedMemorySize, smem);

    coeff_kernel<<<(NUM_NEURONS * 16) / 256, 256>>>(w);
    logic_kernel<<<GRIDB, THREADS, smem>>>(x, conn, out);
}